// round 16
// baseline (speedup 1.0000x reference)
#include <cuda_runtime.h>
#include <cuda_fp16.h>
#include <cstdint>
#include <cstddef>

#define Bb 256
#define Tt 512
#define Ii 64
#define Hh 512
#define Gg 2048   // 4*H

// ---------------- mma.sync / ldmatrix helpers (baseline PTX, sm_80+) -------
__device__ __forceinline__ void mma_f16(float* d, const uint32_t* a, const uint32_t* b) {
    asm volatile(
        "mma.sync.aligned.m16n8k16.row.col.f32.f16.f16.f32 "
        "{%0,%1,%2,%3}, {%4,%5,%6,%7}, {%8,%9}, {%0,%1,%2,%3};"
        : "+f"(d[0]), "+f"(d[1]), "+f"(d[2]), "+f"(d[3])
        : "r"(a[0]), "r"(a[1]), "r"(a[2]), "r"(a[3]), "r"(b[0]), "r"(b[1]));
}
__device__ __forceinline__ void ldsm4(uint32_t* r, uint32_t addr) {
    asm volatile("ldmatrix.sync.aligned.m8n8.x4.shared.b16 {%0,%1,%2,%3}, [%4];"
        : "=r"(r[0]), "=r"(r[1]), "=r"(r[2]), "=r"(r[3]) : "r"(addr));
}
__device__ __forceinline__ uint32_t h2u(__half2 v) {
    return *reinterpret_cast<uint32_t*>(&v);
}
__device__ __forceinline__ uint32_t smem_u32_of(const void* p) {
    uint32_t a;
    asm("{ .reg .u64 t; cvta.to.shared.u64 t, %1; cvt.u32.u64 %0, t; }" : "=r"(a) : "l"(p));
    return a;
}
__device__ __forceinline__ void cpa16(uint32_t dst, const void* src) {
    asm volatile("cp.async.cg.shared.global [%0], [%1], 16;"
                 :: "r"(dst), "l"(src) : "memory");
}
#define CP_COMMIT() asm volatile("cp.async.commit_group;" ::: "memory")
#define CP_WAIT0()  asm volatile("cp.async.wait_group 0;" ::: "memory")
#define CP_WAIT1()  asm volatile("cp.async.wait_group 1;" ::: "memory")

// MUFU activations (tanh.approx, sm_75+ baseline PTX)
__device__ __forceinline__ float tanh_ap(float x) {
    float y; asm("tanh.approx.f32 %0, %1;" : "=f"(y) : "f"(x)); return y;
}
__device__ __forceinline__ float sigmoid_ap(float x) {
    return fmaf(tanh_ap(0.5f * x), 0.5f, 0.5f);
}

// ---------------- static device scratch ------------------------------------
__device__ float  g_xg[(size_t)Bb * Tt * Gg / 2]; // 512 MiB gate pre-acts (fp16)
__device__ __half g_hseq[(size_t)Bb * Tt * Hh];   // 128 MiB layer-0 hidden (fp16)
__device__ __half g_hbuf[2 * (size_t)Bb * Hh];    // double-buffered h (fp16)
__device__ unsigned int g_bar[4];                 // per-M-group barrier counters

__global__ void init_kernel() {
    unsigned idx = blockIdx.x * blockDim.x + threadIdx.x;
    reinterpret_cast<unsigned int*>(g_hbuf)[idx] = 0u;
    if (idx < 4) g_bar[idx] = 0u;
}

// ================= fp16 mma GEMM (f32 inputs; ldmatrix frags) ===============
#define GPH 40
#define SABUF_H (128 * GPH)
#define GEMM_SMEM_BYTES (4 * SABUF_H * 2)

__global__ void __launch_bounds__(256, 2)
mma_gemm(const float* __restrict__ A, const float* __restrict__ W,
         const float* __restrict__ b1, const float* __restrict__ b2,
         __half* __restrict__ C, int K)
{
    extern __shared__ __half smh[];
    __half* sA = smh;
    __half* sB = smh + 2 * SABUF_H;

    const int tid = threadIdx.x;
    const int lane = tid & 31;
    const int wid = tid >> 5;
    const int gid = lane >> 2;
    const int tq = lane & 3;
    const int warpM = wid >> 2;
    const int warpN = wid & 3;
    const size_t n0 = (size_t)blockIdx.x * 128;
    const size_t m0 = (size_t)blockIdx.y * 128;
    const int NC = K >> 5;

    const int lrow = tid >> 3;
    const int lq = tid & 7;

    // ldmatrix lane->address mapping (loop-invariant)
    const uint32_t sA_u = smem_u32_of(sA);
    const uint32_t sB_u = smem_u32_of(sB);
    const int arow = lane & 15, akoff = (lane >> 4) * 8;
    const int bnt = (lane >> 4) & 1, bko = ((lane >> 3) & 1) * 8, brow = lane & 7;
    const uint32_t aBase = sA_u + (((warpM * 64 + arow) * GPH) + akoff) * 2;
    const uint32_t bBase = sB_u + (((warpN * 32 + bnt * 8 + brow) * GPH) + bko) * 2;

    float acc[4][4][4];
#pragma unroll
    for (int mt = 0; mt < 4; ++mt)
#pragma unroll
        for (int nt = 0; nt < 4; ++nt)
#pragma unroll
            for (int k = 0; k < 4; ++k) acc[mt][nt][k] = 0.f;

    float4 pa[4], pb[4];
#pragma unroll
    for (int i = 0; i < 4; ++i) {
        int row = lrow + i * 32;
        pa[i] = *reinterpret_cast<const float4*>(&A[(m0 + row) * (size_t)K + lq * 4]);
        pb[i] = *reinterpret_cast<const float4*>(&W[(n0 + row) * (size_t)K + lq * 4]);
    }
#pragma unroll
    for (int i = 0; i < 4; ++i) {
        int row = lrow + i * 32;
        uint2 ua, ub;
        ua.x = h2u(__floats2half2_rn(pa[i].x, pa[i].y));
        ua.y = h2u(__floats2half2_rn(pa[i].z, pa[i].w));
        ub.x = h2u(__floats2half2_rn(pb[i].x, pb[i].y));
        ub.y = h2u(__floats2half2_rn(pb[i].z, pb[i].w));
        *reinterpret_cast<uint2*>(&sA[row * GPH + lq * 4]) = ua;
        *reinterpret_cast<uint2*>(&sB[row * GPH + lq * 4]) = ub;
    }
    __syncthreads();

#pragma unroll 1
    for (int c = 0; c < NC; ++c) {
        const int buf = c & 1;
        if (c + 1 < NC) {
            int k0 = (c + 1) * 32;
#pragma unroll
            for (int i = 0; i < 4; ++i) {
                int row = lrow + i * 32;
                pa[i] = *reinterpret_cast<const float4*>(&A[(m0 + row) * (size_t)K + k0 + lq * 4]);
                pb[i] = *reinterpret_cast<const float4*>(&W[(n0 + row) * (size_t)K + k0 + lq * 4]);
            }
        }
        const uint32_t aOff = aBase + buf * (SABUF_H * 2);
        const uint32_t bOff = bBase + buf * (SABUF_H * 2);
#pragma unroll
        for (int kk = 0; kk < 2; ++kk) {
            uint32_t a[4][4], bb[2][4];
#pragma unroll
            for (int mt = 0; mt < 4; ++mt)
                ldsm4(a[mt], aOff + kk * 32 + mt * (16 * GPH * 2));
            ldsm4(bb[0], bOff + kk * 32);
            ldsm4(bb[1], bOff + kk * 32 + 16 * GPH * 2);
#pragma unroll
            for (int mt = 0; mt < 4; ++mt) {
                mma_f16(acc[mt][0], a[mt], &bb[0][0]);
                mma_f16(acc[mt][1], a[mt], &bb[0][2]);
                mma_f16(acc[mt][2], a[mt], &bb[1][0]);
                mma_f16(acc[mt][3], a[mt], &bb[1][2]);
            }
        }
        __syncthreads();
        if (c + 1 < NC) {
            __half* dA = sA + (buf ^ 1) * SABUF_H;
            __half* dB = sB + (buf ^ 1) * SABUF_H;
#pragma unroll
            for (int i = 0; i < 4; ++i) {
                int row = lrow + i * 32;
                uint2 ua, ub;
                ua.x = h2u(__floats2half2_rn(pa[i].x, pa[i].y));
                ua.y = h2u(__floats2half2_rn(pa[i].z, pa[i].w));
                ub.x = h2u(__floats2half2_rn(pb[i].x, pb[i].y));
                ub.y = h2u(__floats2half2_rn(pb[i].z, pb[i].w));
                *reinterpret_cast<uint2*>(&dA[row * GPH + lq * 4]) = ua;
                *reinterpret_cast<uint2*>(&dB[row * GPH + lq * 4]) = ub;
            }
            __syncthreads();
        }
    }

    float bias[4][2];
#pragma unroll
    for (int nt = 0; nt < 4; ++nt) {
        size_t ncol = n0 + warpN * 32 + nt * 8 + tq * 2;
        bias[nt][0] = b1[ncol] + b2[ncol];
        bias[nt][1] = b1[ncol + 1] + b2[ncol + 1];
    }
#pragma unroll
    for (int mt = 0; mt < 4; ++mt) {
        size_t r0 = m0 + warpM * 64 + mt * 16 + gid;
#pragma unroll
        for (int nt = 0; nt < 4; ++nt) {
            size_t ncol = n0 + warpN * 32 + nt * 8 + tq * 2;
            uint32_t u0 = h2u(__floats2half2_rn(acc[mt][nt][0] + bias[nt][0],
                                                acc[mt][nt][1] + bias[nt][1]));
            uint32_t u1 = h2u(__floats2half2_rn(acc[mt][nt][2] + bias[nt][0],
                                                acc[mt][nt][3] + bias[nt][1]));
            *reinterpret_cast<uint32_t*>(&C[r0 * Gg + ncol]) = u0;
            *reinterpret_cast<uint32_t*>(&C[(r0 + 8) * Gg + ncol]) = u1;
        }
    }
}

// ================= fp16 mma GEMM, A already fp16 (layer 1) ==================
__global__ void __launch_bounds__(256, 2)
mma_gemm_h(const __half* __restrict__ A, const float* __restrict__ W,
           const float* __restrict__ b1, const float* __restrict__ b2,
           __half* __restrict__ C, int K)
{
    extern __shared__ __half smh[];
    __half* sA = smh;
    __half* sB = smh + 2 * SABUF_H;

    const int tid = threadIdx.x;
    const int lane = tid & 31;
    const int wid = tid >> 5;
    const int gid = lane >> 2;
    const int tq = lane & 3;
    const int warpM = wid >> 2;
    const int warpN = wid & 3;
    const size_t n0 = (size_t)blockIdx.x * 128;
    const size_t m0 = (size_t)blockIdx.y * 128;
    const int NC = K >> 5;

    const int lrow = tid >> 3;
    const int lq = tid & 7;

    const uint32_t sA_u = smem_u32_of(sA);
    const uint32_t sB_u = smem_u32_of(sB);
    const int arow = lane & 15, akoff = (lane >> 4) * 8;
    const int bnt = (lane >> 4) & 1, bko = ((lane >> 3) & 1) * 8, brow = lane & 7;
    const uint32_t aBase = sA_u + (((warpM * 64 + arow) * GPH) + akoff) * 2;
    const uint32_t bBase = sB_u + (((warpN * 32 + bnt * 8 + brow) * GPH) + bko) * 2;

    float acc[4][4][4];
#pragma unroll
    for (int mt = 0; mt < 4; ++mt)
#pragma unroll
        for (int nt = 0; nt < 4; ++nt)
#pragma unroll
            for (int k = 0; k < 4; ++k) acc[mt][nt][k] = 0.f;

    uint2 pa[4];
    float4 pb[4];
#pragma unroll
    for (int i = 0; i < 4; ++i) {
        int row = lrow + i * 32;
        pa[i] = *reinterpret_cast<const uint2*>(&A[(m0 + row) * (size_t)K + lq * 4]);
        pb[i] = *reinterpret_cast<const float4*>(&W[(n0 + row) * (size_t)K + lq * 4]);
    }
#pragma unroll
    for (int i = 0; i < 4; ++i) {
        int row = lrow + i * 32;
        uint2 ub;
        ub.x = h2u(__floats2half2_rn(pb[i].x, pb[i].y));
        ub.y = h2u(__floats2half2_rn(pb[i].z, pb[i].w));
        *reinterpret_cast<uint2*>(&sA[row * GPH + lq * 4]) = pa[i];
        *reinterpret_cast<uint2*>(&sB[row * GPH + lq * 4]) = ub;
    }
    __syncthreads();

#pragma unroll 1
    for (int c = 0; c < NC; ++c) {
        const int buf = c & 1;
        if (c + 1 < NC) {
            int k0 = (c + 1) * 32;
#pragma unroll
            for (int i = 0; i < 4; ++i) {
                int row = lrow + i * 32;
                pa[i] = *reinterpret_cast<const uint2*>(&A[(m0 + row) * (size_t)K + k0 + lq * 4]);
                pb[i] = *reinterpret_cast<const float4*>(&W[(n0 + row) * (size_t)K + k0 + lq * 4]);
            }
        }
        const uint32_t aOff = aBase + buf * (SABUF_H * 2);
        const uint32_t bOff = bBase + buf * (SABUF_H * 2);
#pragma unroll
        for (int kk = 0; kk < 2; ++kk) {
            uint32_t a[4][4], bb[2][4];
#pragma unroll
            for (int mt = 0; mt < 4; ++mt)
                ldsm4(a[mt], aOff + kk * 32 + mt * (16 * GPH * 2));
            ldsm4(bb[0], bOff + kk * 32);
            ldsm4(bb[1], bOff + kk * 32 + 16 * GPH * 2);
#pragma unroll
            for (int mt = 0; mt < 4; ++mt) {
                mma_f16(acc[mt][0], a[mt], &bb[0][0]);
                mma_f16(acc[mt][1], a[mt], &bb[0][2]);
                mma_f16(acc[mt][2], a[mt], &bb[1][0]);
                mma_f16(acc[mt][3], a[mt], &bb[1][2]);
            }
        }
        __syncthreads();
        if (c + 1 < NC) {
            __half* dA = sA + (buf ^ 1) * SABUF_H;
            __half* dB = sB + (buf ^ 1) * SABUF_H;
#pragma unroll
            for (int i = 0; i < 4; ++i) {
                int row = lrow + i * 32;
                uint2 ub;
                ub.x = h2u(__floats2half2_rn(pb[i].x, pb[i].y));
                ub.y = h2u(__floats2half2_rn(pb[i].z, pb[i].w));
                *reinterpret_cast<uint2*>(&dA[row * GPH + lq * 4]) = pa[i];
                *reinterpret_cast<uint2*>(&dB[row * GPH + lq * 4]) = ub;
            }
            __syncthreads();
        }
    }

    float bias[4][2];
#pragma unroll
    for (int nt = 0; nt < 4; ++nt) {
        size_t ncol = n0 + warpN * 32 + nt * 8 + tq * 2;
        bias[nt][0] = b1[ncol] + b2[ncol];
        bias[nt][1] = b1[ncol + 1] + b2[ncol + 1];
    }
#pragma unroll
    for (int mt = 0; mt < 4; ++mt) {
        size_t r0 = m0 + warpM * 64 + mt * 16 + gid;
#pragma unroll
        for (int nt = 0; nt < 4; ++nt) {
            size_t ncol = n0 + warpN * 32 + nt * 8 + tq * 2;
            uint32_t u0 = h2u(__floats2half2_rn(acc[mt][nt][0] + bias[nt][0],
                                                acc[mt][nt][1] + bias[nt][1]));
            uint32_t u1 = h2u(__floats2half2_rn(acc[mt][nt][2] + bias[nt][0],
                                                acc[mt][nt][3] + bias[nt][1]));
            *reinterpret_cast<uint32_t*>(&C[r0 * Gg + ncol]) = u0;
            *reinterpret_cast<uint32_t*>(&C[(r0 + 8) * Gg + ncol]) = u1;
        }
    }
}

// ================= persistent LSTM recurrence ================================
// fp16 mma with ldmatrix fragment loads; split-half pipelined staging;
// symmetric K-split epilogue; MUFU activations; fp16 hseq; warp-granular
// per-M-group barrier.
#define NCTA_R 128
#define GRP_ARR 256                      // 32 CTAs x 8 warps
#define RWPH 520
#define RHPH 520
#define XGPH 72
#define SM_W_BYTES   (64 * RWPH * 2)     // 66560
#define SM_H_BYTES   (64 * RHPH * 2)     // 66560
#define SM_XG_BYTES  (64 * XGPH * 2)     // 9216
#define SM_RED_BYTES (4096 * 4)          // 16384
#define SM_TRH_BYTES (64 * 16 * 2)       // 2048
#define REC_SMEM_BYTES (SM_W_BYTES + SM_H_BYTES + SM_XG_BYTES + SM_RED_BYTES + \
                        SM_TRH_BYTES)    // 160768

__global__ void __launch_bounds__(256, 1)
lstm_rec(const float* __restrict__ W_hh, const __half* __restrict__ xgh,
         __half* __restrict__ hseq)
{
    extern __shared__ char smc[];
    __half* sWh  = reinterpret_cast<__half*>(smc);
    __half* sHh  = reinterpret_cast<__half*>(smc + SM_W_BYTES);
    __half* sXG  = reinterpret_cast<__half*>(smc + SM_W_BYTES + SM_H_BYTES);
    float*  sRed = reinterpret_cast<float*>(smc + SM_W_BYTES + SM_H_BYTES + SM_XG_BYTES);
    __half* sTrH = reinterpret_cast<__half*>(smc + SM_W_BYTES + SM_H_BYTES + SM_XG_BYTES + SM_RED_BYTES);

    const uint32_t sH_u  = smem_u32_of(sHh);
    const uint32_t sW_u  = smem_u32_of(sWh);
    const uint32_t sXG_u = smem_u32_of(sXG);

    const int tid = threadIdx.x;
    const int lane = tid & 31;
    const int wid = tid >> 5;
    const int wK = wid >> 2;              // == half; owns mt=wK
    const int wM = (wid >> 1) & 1;
    const int wN = wid & 1;
    const int gid = lane >> 2;
    const int tq = lane & 3;
    const int p = lane & 1;

    const int ctaM = blockIdx.x & 3;
    const int ctaC = blockIdx.x >> 2;
    const int m0 = ctaM * 64;
    const int hc0 = ctaC * 16;

    const int half = tid >> 7;
    const int st = tid & 127;
    const int hcolh = half * 256;
    const int hcolb = half * 512;
    const int barid = 1 + half;

    // ldmatrix lane->address mapping (loop-invariant; single h buffer)
    const int arow = lane & 15, akoff = (lane >> 4) * 8;
    const int bnt = (lane >> 4) & 1, bko = ((lane >> 3) & 1) * 8, brow = lane & 7;
    const uint32_t aAddr0 = sH_u + (((wM * 32 + arow) * RHPH) + wK * 256 + akoff) * 2;
    const uint32_t aAddr1 = aAddr0 + 16 * (RHPH * 2);
    const uint32_t bAddr0 = sW_u + (((wN * 32 + bnt * 8 + brow) * RWPH) + wK * 256 + bko) * 2;
    const uint32_t bAddr1 = bAddr0 + 16 * (RWPH * 2);

    // W_hh slice -> smem (fp16 rne), row j = cl*4 + g
    for (int idx = tid; idx < 64 * 512; idx += 256) {
        int j = idx >> 9, k = idx & 511;
        sWh[j * RWPH + k] =
            __float2half_rn(W_hh[((size_t)(j & 3) * Hh + hc0 + (j >> 2)) * Hh + k]);
    }
    __syncthreads();

    float cst[4];
#pragma unroll
    for (int s = 0; s < 4; ++s) cst[s] = 0.f;
    unsigned phase = 0;
    const int pair = wM * 2 + wN;

    // ---- xg(0) cp.async ----
#pragma unroll
    for (int it = 0; it < 2; ++it) {
        int seg = tid + it * 256;
        int row = seg >> 3, c8 = seg & 7;
        int gate = c8 >> 1, colpart = (c8 & 1) * 8;
        cpa16(sXG_u + (row * XGPH + c8 * 8) * 2,
              &xgh[((size_t)(m0 + row) * Tt + 0) * Gg + (size_t)gate * Hh + hc0 + colpart]);
    }
    CP_COMMIT();

    for (int t = 0; t < Tt; ++t) {
        const __half* hin = g_hbuf + (size_t)(t & 1) * Bb * Hh;
        __half* hout = g_hbuf + (size_t)((t + 1) & 1) * Bb * Hh;

        // ---- stage this half's 64x256 h region in TWO commit groups ----
#pragma unroll
        for (int it = 0; it < 8; ++it) {
            int seg = st + it * 128;
            int row = seg >> 4, c16 = seg & 15;
            cpa16(sH_u + row * (RHPH * 2) + hcolb + c16 * 16,
                  hin + (size_t)(m0 + row) * Hh + hcolh + c16 * 8);
        }
        CP_COMMIT();
#pragma unroll
        for (int it = 0; it < 8; ++it) {
            int seg = st + it * 128;
            int row = seg >> 4, c16 = (seg & 15) + 16;
            cpa16(sH_u + row * (RHPH * 2) + hcolb + c16 * 16,
                  hin + (size_t)(m0 + row) * Hh + hcolh + c16 * 8);
        }
        CP_COMMIT();

        float acc[2][4][4];
#pragma unroll
        for (int mt = 0; mt < 2; ++mt)
#pragma unroll
            for (int nt = 0; nt < 4; ++nt)
#pragma unroll
                for (int k = 0; k < 4; ++k) acc[mt][nt][k] = 0.f;

        CP_WAIT1();
        asm volatile("bar.sync %0, 128;" :: "r"(barid) : "memory");
#pragma unroll
        for (int kk = 0; kk < 8; ++kk) {
            uint32_t a0[4], a1[4], b0[4], b1[4];
            ldsm4(a0, aAddr0 + kk * 32);
            ldsm4(a1, aAddr1 + kk * 32);
            ldsm4(b0, bAddr0 + kk * 32);
            ldsm4(b1, bAddr1 + kk * 32);
            mma_f16(acc[0][0], a0, &b0[0]);
            mma_f16(acc[0][1], a0, &b0[2]);
            mma_f16(acc[0][2], a0, &b1[0]);
            mma_f16(acc[0][3], a0, &b1[2]);
            mma_f16(acc[1][0], a1, &b0[0]);
            mma_f16(acc[1][1], a1, &b0[2]);
            mma_f16(acc[1][2], a1, &b1[0]);
            mma_f16(acc[1][3], a1, &b1[2]);
        }
        CP_WAIT0();
        asm volatile("bar.sync %0, 128;" :: "r"(barid) : "memory");
#pragma unroll
        for (int kk = 8; kk < 16; ++kk) {
            uint32_t a0[4], a1[4], b0[4], b1[4];
            ldsm4(a0, aAddr0 + kk * 32);
            ldsm4(a1, aAddr1 + kk * 32);
            ldsm4(b0, bAddr0 + kk * 32);
            ldsm4(b1, bAddr1 + kk * 32);
            mma_f16(acc[0][0], a0, &b0[0]);
            mma_f16(acc[0][1], a0, &b0[2]);
            mma_f16(acc[0][2], a0, &b1[0]);
            mma_f16(acc[0][3], a0, &b1[2]);
            mma_f16(acc[1][0], a1, &b0[0]);
            mma_f16(acc[1][1], a1, &b0[2]);
            mma_f16(acc[1][2], a1, &b1[0]);
            mma_f16(acc[1][3], a1, &b1[2]);
        }

        // ---- symmetric K-split exchange: write NON-owned mt to sRed ----
        {
            int mtx = wK ^ 1;
#pragma unroll
            for (int nt = 0; nt < 4; ++nt) {
                float4 v;
                v.x = acc[mtx][nt][0]; v.y = acc[mtx][nt][1];
                v.z = acc[mtx][nt][2]; v.w = acc[mtx][nt][3];
                *reinterpret_cast<float4*>(
                    &sRed[((wK * 4 + pair) * 4 + nt) * 128 + lane * 4]) = v;
            }
        }
        __syncthreads();                   // (2)

        // ---- finalize owned mt: add peer partials, activations, write tile
        {
            int mto = wK;
            int src = wK ^ 1;
            int rl = wM * 32 + mto * 16 + gid + p * 8;
#pragma unroll
            for (int nt = 0; nt < 4; ++nt) {
                float4 v = *reinterpret_cast<const float4*>(
                    &sRed[((src * 4 + pair) * 4 + nt) * 128 + lane * 4]);
                float q0 = acc[mto][nt][0] + v.x;
                float q1 = acc[mto][nt][1] + v.y;
                float q2 = acc[mto][nt][2] + v.z;
                float q3 = acc[mto][nt][3] + v.w;
                float s0 = p ? q0 : q2;
                float s1 = p ? q1 : q3;
                float r0 = __shfl_xor_sync(0xffffffffu, s0, 1);
                float r1 = __shfl_xor_sync(0xffffffffu, s1, 1);
                float gi = p ? r0 : q0;
                float gf = p ? r1 : q1;
                float gg = p ? q2 : r0;
                float go = p ? q3 : r1;
                int cl = wN * 8 + nt * 2 + (tq >> 1);
                const __half* xp = &sXG[rl * XGPH + cl];
                float iv = sigmoid_ap(gi + __half2float(xp[0]));
                float fv = sigmoid_ap(gf + __half2float(xp[16]));
                float gv = tanh_ap(gg + __half2float(xp[32]));
                float ov = sigmoid_ap(go + __half2float(xp[48]));
                cst[nt] = fv * cst[nt] + iv * gv;
                float hv = ov * tanh_ap(cst[nt]);
                sTrH[rl * 16 + cl] = __float2half_rn(hv);
            }
        }
        __syncthreads();                   // (2b) sTrH complete; sXG consumed

        // ---- coalesced hout write (each warp its own 8 rows) ----
        {
            int row = tid >> 2, part = tid & 3;
            uint2 v = *reinterpret_cast<const uint2*>(&sTrH[row * 16 + part * 4]);
            *reinterpret_cast<uint2*>(&hout[(size_t)(m0 + row) * Hh + hc0 + part * 4]) = v;
        }

        // ---- warp-granular arrive (release covers this warp's hout) ----
        phase += GRP_ARR;
        __syncwarp();
        if (lane == 0) {
            asm volatile("red.release.gpu.add.u32 [%0], %1;"
                         :: "l"(&g_bar[ctaM]), "r"(1u) : "memory");
        }

        // ---- non-critical work in barrier shadow: hseq + xg(t+1) ----
        if (hseq) {
            int row = tid >> 2, part = tid & 3;
            uint2 v = *reinterpret_cast<const uint2*>(&sTrH[row * 16 + part * 4]);
            *reinterpret_cast<uint2*>(
                &hseq[((size_t)(m0 + row) * Tt + t) * Hh + hc0 + part * 4]) = v;
        }
        if (t + 1 < Tt) {
#pragma unroll
            for (int it = 0; it < 2; ++it) {
                int seg = tid + it * 256;
                int row = seg >> 3, c8 = seg & 7;
                int gate = c8 >> 1, colpart = (c8 & 1) * 8;
                cpa16(sXG_u + (row * XGPH + c8 * 8) * 2,
                      &xgh[((size_t)(m0 + row) * Tt + (t + 1)) * Gg
                           + (size_t)gate * Hh + hc0 + colpart]);
            }
            CP_COMMIT();
        }

        // ---- per-warp acquire-poll ----
        if (lane == 0) {
            unsigned v;
            do {
                asm volatile("ld.acquire.gpu.u32 %0, [%1];"
                             : "=r"(v) : "l"(&g_bar[ctaM]) : "memory");
            } while (v < phase);
        }
        __syncwarp();
    }
}

// ---------------- final FC (h is fp16) --------------------------------------
__global__ void fc_kernel(const __half* __restrict__ h, const float* __restrict__ Wfc,
                          const float* __restrict__ bfc, float* __restrict__ out)
{
    int b = blockIdx.x;
    int tid = threadIdx.x;
    float s = 0.f;
    for (int k = tid; k < Hh; k += 128)
        s += __half2float(h[(size_t)b * Hh + k]) * Wfc[k];
#pragma unroll
    for (int o = 16; o > 0; o >>= 1) s += __shfl_xor_sync(0xffffffffu, s, o);
    __shared__ float ws[4];
    if ((tid & 31) == 0) ws[tid >> 5] = s;
    __syncthreads();
    if (tid == 0) out[b] = ws[0] + ws[1] + ws[2] + ws[3] + bfc[0];
}

// ---------------- launch ----------------------------------------------------
extern "C" void kernel_launch(void* const* d_in, const int* in_sizes, int n_in,
                              void* d_out, int out_size)
{
    (void)in_sizes; (void)n_in; (void)out_size;
    const float* x     = (const float*)d_in[0];
    const float* W_ih0 = (const float*)d_in[1];
    const float* W_hh0 = (const float*)d_in[2];
    const float* b_ih0 = (const float*)d_in[3];
    const float* b_hh0 = (const float*)d_in[4];
    const float* W_ih1 = (const float*)d_in[5];
    const float* W_hh1 = (const float*)d_in[6];
    const float* b_ih1 = (const float*)d_in[7];
    const float* b_hh1 = (const float*)d_in[8];
    const float* W_fc  = (const float*)d_in[9];
    const float* b_fc  = (const float*)d_in[10];
    float* out = (float*)d_out;

    void *p_xg = nullptr, *p_hseq = nullptr, *p_hbuf = nullptr;
    cudaGetSymbolAddress(&p_xg, g_xg);
    cudaGetSymbolAddress(&p_hseq, g_hseq);
    cudaGetSymbolAddress(&p_hbuf, g_hbuf);

    cudaFuncSetAttribute(mma_gemm, cudaFuncAttributeMaxDynamicSharedMemorySize,
                         GEMM_SMEM_BYTES);
    cudaFuncSetAttribute(mma_gemm_h, cudaFuncAttributeMaxDynamicSharedMemorySize,
                         GEMM_SMEM_BYTES);
    cudaFuncSetAttribute(lstm_rec, cudaFuncAttributeMaxDynamicSharedMemorySize,
                         REC_SMEM_BYTES);

    dim3 ggrid(Gg / 128, (Bb * Tt) / 128);   // (16, 1024)

    // Layer 0
    mma_gemm<<<ggrid, 256, GEMM_SMEM_BYTES>>>(x, W_ih0, b_ih0, b_hh0,
                                              (__half*)p_xg, Ii);
    init_kernel<<<1024, 256>>>();
    lstm_rec<<<NCTA_R, 256, REC_SMEM_BYTES>>>(W_hh0, (const __half*)p_xg,
                                              (__half*)p_hseq);

    // Layer 1 (A = fp16 hseq)
    mma_gemm_h<<<ggrid, 256, GEMM_SMEM_BYTES>>>((const __half*)p_hseq, W_ih1,
                                                b_ih1, b_hh1, (__half*)p_xg, Hh);
    init_kernel<<<1024, 256>>>();
    lstm_rec<<<NCTA_R, 256, REC_SMEM_BYTES>>>(W_hh1, (const __half*)p_xg, nullptr);

    // Final FC (h_last ends in buffer 0 since T=512 is even; fp16 layout)
    fc_kernel<<<Bb, 128>>>((const __half*)p_hbuf, W_fc, b_fc, out);
}

// round 17
// speedup vs baseline: 1.0986x; 1.0986x over previous
#include <cuda_runtime.h>
#include <cuda_fp16.h>
#include <cstdint>
#include <cstddef>

#define Bb 256
#define Tt 512
#define Ii 64
#define Hh 512
#define Gg 2048   // 4*H

// ---------------- mma.sync / ldmatrix helpers (baseline PTX, sm_80+) -------
__device__ __forceinline__ void mma_f16(float* d, const uint32_t* a, const uint32_t* b) {
    asm volatile(
        "mma.sync.aligned.m16n8k16.row.col.f32.f16.f16.f32 "
        "{%0,%1,%2,%3}, {%4,%5,%6,%7}, {%8,%9}, {%0,%1,%2,%3};"
        : "+f"(d[0]), "+f"(d[1]), "+f"(d[2]), "+f"(d[3])
        : "r"(a[0]), "r"(a[1]), "r"(a[2]), "r"(a[3]), "r"(b[0]), "r"(b[1]));
}
__device__ __forceinline__ void ldsm4(uint32_t* r, uint32_t addr) {
    asm volatile("ldmatrix.sync.aligned.m8n8.x4.shared.b16 {%0,%1,%2,%3}, [%4];"
        : "=r"(r[0]), "=r"(r[1]), "=r"(r[2]), "=r"(r[3]) : "r"(addr));
}
__device__ __forceinline__ uint32_t ldu32(const __half* p) {
    return *reinterpret_cast<const uint32_t*>(p);
}
__device__ __forceinline__ uint32_t h2u(__half2 v) {
    return *reinterpret_cast<uint32_t*>(&v);
}
__device__ __forceinline__ uint32_t smem_u32_of(const void* p) {
    uint32_t a;
    asm("{ .reg .u64 t; cvta.to.shared.u64 t, %1; cvt.u32.u64 %0, t; }" : "=r"(a) : "l"(p));
    return a;
}
__device__ __forceinline__ void cpa16(uint32_t dst, const void* src) {
    asm volatile("cp.async.cg.shared.global [%0], [%1], 16;"
                 :: "r"(dst), "l"(src) : "memory");
}
#define CP_COMMIT() asm volatile("cp.async.commit_group;" ::: "memory")
#define CP_WAIT0()  asm volatile("cp.async.wait_group 0;" ::: "memory")
#define CP_WAIT1()  asm volatile("cp.async.wait_group 1;" ::: "memory")

// MUFU activations (tanh.approx, sm_75+ baseline PTX)
__device__ __forceinline__ float tanh_ap(float x) {
    float y; asm("tanh.approx.f32 %0, %1;" : "=f"(y) : "f"(x)); return y;
}
__device__ __forceinline__ float sigmoid_ap(float x) {
    return fmaf(tanh_ap(0.5f * x), 0.5f, 0.5f);
}

// ---------------- static device scratch ------------------------------------
__device__ float  g_xg[(size_t)Bb * Tt * Gg / 2]; // 512 MiB gate pre-acts (fp16)
__device__ __half g_hseq[(size_t)Bb * Tt * Hh];   // 128 MiB layer-0 hidden (fp16)
__device__ __half g_hbuf[2 * (size_t)Bb * Hh];    // double-buffered h (fp16)
__device__ unsigned int g_bar[4];                 // per-M-group barrier counters

__global__ void init_kernel() {
    unsigned idx = blockIdx.x * blockDim.x + threadIdx.x;
    reinterpret_cast<unsigned int*>(g_hbuf)[idx] = 0u;
    if (idx < 4) g_bar[idx] = 0u;
}

// ================= fp16 mma GEMM (f32 inputs; ldmatrix frags) ===============
#define GPH 40
#define SABUF_H (128 * GPH)
#define GEMM_SMEM_BYTES (4 * SABUF_H * 2)

__global__ void __launch_bounds__(256, 2)
mma_gemm(const float* __restrict__ A, const float* __restrict__ W,
         const float* __restrict__ b1, const float* __restrict__ b2,
         __half* __restrict__ C, int K)
{
    extern __shared__ __half smh[];
    __half* sA = smh;
    __half* sB = smh + 2 * SABUF_H;

    const int tid = threadIdx.x;
    const int lane = tid & 31;
    const int wid = tid >> 5;
    const int gid = lane >> 2;
    const int tq = lane & 3;
    const int warpM = wid >> 2;
    const int warpN = wid & 3;
    const size_t n0 = (size_t)blockIdx.x * 128;
    const size_t m0 = (size_t)blockIdx.y * 128;
    const int NC = K >> 5;

    const int lrow = tid >> 3;
    const int lq = tid & 7;

    // ldmatrix lane->address mapping (loop-invariant)
    const uint32_t sA_u = smem_u32_of(sA);
    const uint32_t sB_u = smem_u32_of(sB);
    const int arow = lane & 15, akoff = (lane >> 4) * 8;
    const int bnt = (lane >> 4) & 1, bko = ((lane >> 3) & 1) * 8, brow = lane & 7;
    const uint32_t aBase = sA_u + (((warpM * 64 + arow) * GPH) + akoff) * 2;
    const uint32_t bBase = sB_u + (((warpN * 32 + bnt * 8 + brow) * GPH) + bko) * 2;

    float acc[4][4][4];
#pragma unroll
    for (int mt = 0; mt < 4; ++mt)
#pragma unroll
        for (int nt = 0; nt < 4; ++nt)
#pragma unroll
            for (int k = 0; k < 4; ++k) acc[mt][nt][k] = 0.f;

    float4 pa[4], pb[4];
#pragma unroll
    for (int i = 0; i < 4; ++i) {
        int row = lrow + i * 32;
        pa[i] = *reinterpret_cast<const float4*>(&A[(m0 + row) * (size_t)K + lq * 4]);
        pb[i] = *reinterpret_cast<const float4*>(&W[(n0 + row) * (size_t)K + lq * 4]);
    }
#pragma unroll
    for (int i = 0; i < 4; ++i) {
        int row = lrow + i * 32;
        uint2 ua, ub;
        ua.x = h2u(__floats2half2_rn(pa[i].x, pa[i].y));
        ua.y = h2u(__floats2half2_rn(pa[i].z, pa[i].w));
        ub.x = h2u(__floats2half2_rn(pb[i].x, pb[i].y));
        ub.y = h2u(__floats2half2_rn(pb[i].z, pb[i].w));
        *reinterpret_cast<uint2*>(&sA[row * GPH + lq * 4]) = ua;
        *reinterpret_cast<uint2*>(&sB[row * GPH + lq * 4]) = ub;
    }
    __syncthreads();

#pragma unroll 1
    for (int c = 0; c < NC; ++c) {
        const int buf = c & 1;
        if (c + 1 < NC) {
            int k0 = (c + 1) * 32;
#pragma unroll
            for (int i = 0; i < 4; ++i) {
                int row = lrow + i * 32;
                pa[i] = *reinterpret_cast<const float4*>(&A[(m0 + row) * (size_t)K + k0 + lq * 4]);
                pb[i] = *reinterpret_cast<const float4*>(&W[(n0 + row) * (size_t)K + k0 + lq * 4]);
            }
        }
        const uint32_t aOff = aBase + buf * (SABUF_H * 2);
        const uint32_t bOff = bBase + buf * (SABUF_H * 2);
#pragma unroll
        for (int kk = 0; kk < 2; ++kk) {
            uint32_t a[4][4], bb[2][4];
#pragma unroll
            for (int mt = 0; mt < 4; ++mt)
                ldsm4(a[mt], aOff + kk * 32 + mt * (16 * GPH * 2));
            ldsm4(bb[0], bOff + kk * 32);
            ldsm4(bb[1], bOff + kk * 32 + 16 * GPH * 2);
#pragma unroll
            for (int mt = 0; mt < 4; ++mt) {
                mma_f16(acc[mt][0], a[mt], &bb[0][0]);
                mma_f16(acc[mt][1], a[mt], &bb[0][2]);
                mma_f16(acc[mt][2], a[mt], &bb[1][0]);
                mma_f16(acc[mt][3], a[mt], &bb[1][2]);
            }
        }
        __syncthreads();
        if (c + 1 < NC) {
            __half* dA = sA + (buf ^ 1) * SABUF_H;
            __half* dB = sB + (buf ^ 1) * SABUF_H;
#pragma unroll
            for (int i = 0; i < 4; ++i) {
                int row = lrow + i * 32;
                uint2 ua, ub;
                ua.x = h2u(__floats2half2_rn(pa[i].x, pa[i].y));
                ua.y = h2u(__floats2half2_rn(pa[i].z, pa[i].w));
                ub.x = h2u(__floats2half2_rn(pb[i].x, pb[i].y));
                ub.y = h2u(__floats2half2_rn(pb[i].z, pb[i].w));
                *reinterpret_cast<uint2*>(&dA[row * GPH + lq * 4]) = ua;
                *reinterpret_cast<uint2*>(&dB[row * GPH + lq * 4]) = ub;
            }
            __syncthreads();
        }
    }

    float bias[4][2];
#pragma unroll
    for (int nt = 0; nt < 4; ++nt) {
        size_t ncol = n0 + warpN * 32 + nt * 8 + tq * 2;
        bias[nt][0] = b1[ncol] + b2[ncol];
        bias[nt][1] = b1[ncol + 1] + b2[ncol + 1];
    }
#pragma unroll
    for (int mt = 0; mt < 4; ++mt) {
        size_t r0 = m0 + warpM * 64 + mt * 16 + gid;
#pragma unroll
        for (int nt = 0; nt < 4; ++nt) {
            size_t ncol = n0 + warpN * 32 + nt * 8 + tq * 2;
            uint32_t u0 = h2u(__floats2half2_rn(acc[mt][nt][0] + bias[nt][0],
                                                acc[mt][nt][1] + bias[nt][1]));
            uint32_t u1 = h2u(__floats2half2_rn(acc[mt][nt][2] + bias[nt][0],
                                                acc[mt][nt][3] + bias[nt][1]));
            *reinterpret_cast<uint32_t*>(&C[r0 * Gg + ncol]) = u0;
            *reinterpret_cast<uint32_t*>(&C[(r0 + 8) * Gg + ncol]) = u1;
        }
    }
}

// ================= fp16 mma GEMM, A already fp16 (layer 1) ==================
__global__ void __launch_bounds__(256, 2)
mma_gemm_h(const __half* __restrict__ A, const float* __restrict__ W,
           const float* __restrict__ b1, const float* __restrict__ b2,
           __half* __restrict__ C, int K)
{
    extern __shared__ __half smh[];
    __half* sA = smh;
    __half* sB = smh + 2 * SABUF_H;

    const int tid = threadIdx.x;
    const int lane = tid & 31;
    const int wid = tid >> 5;
    const int gid = lane >> 2;
    const int tq = lane & 3;
    const int warpM = wid >> 2;
    const int warpN = wid & 3;
    const size_t n0 = (size_t)blockIdx.x * 128;
    const size_t m0 = (size_t)blockIdx.y * 128;
    const int NC = K >> 5;

    const int lrow = tid >> 3;
    const int lq = tid & 7;

    const uint32_t sA_u = smem_u32_of(sA);
    const uint32_t sB_u = smem_u32_of(sB);
    const int arow = lane & 15, akoff = (lane >> 4) * 8;
    const int bnt = (lane >> 4) & 1, bko = ((lane >> 3) & 1) * 8, brow = lane & 7;
    const uint32_t aBase = sA_u + (((warpM * 64 + arow) * GPH) + akoff) * 2;
    const uint32_t bBase = sB_u + (((warpN * 32 + bnt * 8 + brow) * GPH) + bko) * 2;

    float acc[4][4][4];
#pragma unroll
    for (int mt = 0; mt < 4; ++mt)
#pragma unroll
        for (int nt = 0; nt < 4; ++nt)
#pragma unroll
            for (int k = 0; k < 4; ++k) acc[mt][nt][k] = 0.f;

    uint2 pa[4];
    float4 pb[4];
#pragma unroll
    for (int i = 0; i < 4; ++i) {
        int row = lrow + i * 32;
        pa[i] = *reinterpret_cast<const uint2*>(&A[(m0 + row) * (size_t)K + lq * 4]);
        pb[i] = *reinterpret_cast<const float4*>(&W[(n0 + row) * (size_t)K + lq * 4]);
    }
#pragma unroll
    for (int i = 0; i < 4; ++i) {
        int row = lrow + i * 32;
        uint2 ub;
        ub.x = h2u(__floats2half2_rn(pb[i].x, pb[i].y));
        ub.y = h2u(__floats2half2_rn(pb[i].z, pb[i].w));
        *reinterpret_cast<uint2*>(&sA[row * GPH + lq * 4]) = pa[i];
        *reinterpret_cast<uint2*>(&sB[row * GPH + lq * 4]) = ub;
    }
    __syncthreads();

#pragma unroll 1
    for (int c = 0; c < NC; ++c) {
        const int buf = c & 1;
        if (c + 1 < NC) {
            int k0 = (c + 1) * 32;
#pragma unroll
            for (int i = 0; i < 4; ++i) {
                int row = lrow + i * 32;
                pa[i] = *reinterpret_cast<const uint2*>(&A[(m0 + row) * (size_t)K + k0 + lq * 4]);
                pb[i] = *reinterpret_cast<const float4*>(&W[(n0 + row) * (size_t)K + k0 + lq * 4]);
            }
        }
        const uint32_t aOff = aBase + buf * (SABUF_H * 2);
        const uint32_t bOff = bBase + buf * (SABUF_H * 2);
#pragma unroll
        for (int kk = 0; kk < 2; ++kk) {
            uint32_t a[4][4], bb[2][4];
#pragma unroll
            for (int mt = 0; mt < 4; ++mt)
                ldsm4(a[mt], aOff + kk * 32 + mt * (16 * GPH * 2));
            ldsm4(bb[0], bOff + kk * 32);
            ldsm4(bb[1], bOff + kk * 32 + 16 * GPH * 2);
#pragma unroll
            for (int mt = 0; mt < 4; ++mt) {
                mma_f16(acc[mt][0], a[mt], &bb[0][0]);
                mma_f16(acc[mt][1], a[mt], &bb[0][2]);
                mma_f16(acc[mt][2], a[mt], &bb[1][0]);
                mma_f16(acc[mt][3], a[mt], &bb[1][2]);
            }
        }
        __syncthreads();
        if (c + 1 < NC) {
            __half* dA = sA + (buf ^ 1) * SABUF_H;
            __half* dB = sB + (buf ^ 1) * SABUF_H;
#pragma unroll
            for (int i = 0; i < 4; ++i) {
                int row = lrow + i * 32;
                uint2 ub;
                ub.x = h2u(__floats2half2_rn(pb[i].x, pb[i].y));
                ub.y = h2u(__floats2half2_rn(pb[i].z, pb[i].w));
                *reinterpret_cast<uint2*>(&dA[row * GPH + lq * 4]) = pa[i];
                *reinterpret_cast<uint2*>(&dB[row * GPH + lq * 4]) = ub;
            }
            __syncthreads();
        }
    }

    float bias[4][2];
#pragma unroll
    for (int nt = 0; nt < 4; ++nt) {
        size_t ncol = n0 + warpN * 32 + nt * 8 + tq * 2;
        bias[nt][0] = b1[ncol] + b2[ncol];
        bias[nt][1] = b1[ncol + 1] + b2[ncol + 1];
    }
#pragma unroll
    for (int mt = 0; mt < 4; ++mt) {
        size_t r0 = m0 + warpM * 64 + mt * 16 + gid;
#pragma unroll
        for (int nt = 0; nt < 4; ++nt) {
            size_t ncol = n0 + warpN * 32 + nt * 8 + tq * 2;
            uint32_t u0 = h2u(__floats2half2_rn(acc[mt][nt][0] + bias[nt][0],
                                                acc[mt][nt][1] + bias[nt][1]));
            uint32_t u1 = h2u(__floats2half2_rn(acc[mt][nt][2] + bias[nt][0],
                                                acc[mt][nt][3] + bias[nt][1]));
            *reinterpret_cast<uint32_t*>(&C[r0 * Gg + ncol]) = u0;
            *reinterpret_cast<uint32_t*>(&C[(r0 + 8) * Gg + ncol]) = u1;
        }
    }
}

// ================= persistent LSTM recurrence (R14 fragment loads) ==========
// fp16 mma with LDS.32 fragment loads (validated fastest); split-half
// pipelined staging; symmetric K-split epilogue; MUFU activations; fp16
// hseq; warp-granular per-M-group barrier.
#define NCTA_R 128
#define GRP_ARR 256                      // 32 CTAs x 8 warps
#define RWPH 520
#define RHPH 520
#define XGPH 72
#define SM_W_BYTES   (64 * RWPH * 2)     // 66560
#define SM_H_BYTES   (64 * RHPH * 2)     // 66560
#define SM_XG_BYTES  (64 * XGPH * 2)     // 9216
#define SM_RED_BYTES (4096 * 4)          // 16384
#define SM_TRH_BYTES (64 * 16 * 2)       // 2048
#define REC_SMEM_BYTES (SM_W_BYTES + SM_H_BYTES + SM_XG_BYTES + SM_RED_BYTES + \
                        SM_TRH_BYTES)    // 160768

__global__ void __launch_bounds__(256, 1)
lstm_rec(const float* __restrict__ W_hh, const __half* __restrict__ xgh,
         __half* __restrict__ hseq)
{
    extern __shared__ char smc[];
    __half* sWh  = reinterpret_cast<__half*>(smc);
    __half* sHh  = reinterpret_cast<__half*>(smc + SM_W_BYTES);
    __half* sXG  = reinterpret_cast<__half*>(smc + SM_W_BYTES + SM_H_BYTES);
    float*  sRed = reinterpret_cast<float*>(smc + SM_W_BYTES + SM_H_BYTES + SM_XG_BYTES);
    __half* sTrH = reinterpret_cast<__half*>(smc + SM_W_BYTES + SM_H_BYTES + SM_XG_BYTES + SM_RED_BYTES);

    const uint32_t sH_u  = smem_u32_of(sHh);
    const uint32_t sXG_u = smem_u32_of(sXG);

    const int tid = threadIdx.x;
    const int lane = tid & 31;
    const int wid = tid >> 5;
    const int wK = wid >> 2;              // == half; owns mt=wK
    const int wM = (wid >> 1) & 1;
    const int wN = wid & 1;
    const int gid = lane >> 2;
    const int tq = lane & 3;
    const int p = lane & 1;

    const int ctaM = blockIdx.x & 3;
    const int ctaC = blockIdx.x >> 2;
    const int m0 = ctaM * 64;
    const int hc0 = ctaC * 16;

    const int half = tid >> 7;
    const int st = tid & 127;
    const int hcolh = half * 256;
    const int hcolb = half * 512;
    const int barid = 1 + half;

    // W_hh slice -> smem (fp16 rne), row j = cl*4 + g
    for (int idx = tid; idx < 64 * 512; idx += 256) {
        int j = idx >> 9, k = idx & 511;
        sWh[j * RWPH + k] =
            __float2half_rn(W_hh[((size_t)(j & 3) * Hh + hc0 + (j >> 2)) * Hh + k]);
    }
    __syncthreads();

    float cst[4];
#pragma unroll
    for (int s = 0; s < 4; ++s) cst[s] = 0.f;
    unsigned phase = 0;
    const int pair = wM * 2 + wN;

    // ---- xg(0) cp.async ----
#pragma unroll
    for (int it = 0; it < 2; ++it) {
        int seg = tid + it * 256;
        int row = seg >> 3, c8 = seg & 7;
        int gate = c8 >> 1, colpart = (c8 & 1) * 8;
        cpa16(sXG_u + (row * XGPH + c8 * 8) * 2,
              &xgh[((size_t)(m0 + row) * Tt + 0) * Gg + (size_t)gate * Hh + hc0 + colpart]);
    }
    CP_COMMIT();

    for (int t = 0; t < Tt; ++t) {
        const __half* hin = g_hbuf + (size_t)(t & 1) * Bb * Hh;
        __half* hout = g_hbuf + (size_t)((t + 1) & 1) * Bb * Hh;

        // ---- stage this half's 64x256 h region in TWO commit groups ----
#pragma unroll
        for (int it = 0; it < 8; ++it) {
            int seg = st + it * 128;
            int row = seg >> 4, c16 = seg & 15;
            cpa16(sH_u + row * (RHPH * 2) + hcolb + c16 * 16,
                  hin + (size_t)(m0 + row) * Hh + hcolh + c16 * 8);
        }
        CP_COMMIT();
#pragma unroll
        for (int it = 0; it < 8; ++it) {
            int seg = st + it * 128;
            int row = seg >> 4, c16 = (seg & 15) + 16;
            cpa16(sH_u + row * (RHPH * 2) + hcolb + c16 * 16,
                  hin + (size_t)(m0 + row) * Hh + hcolh + c16 * 8);
        }
        CP_COMMIT();

        float acc[2][4][4];
#pragma unroll
        for (int mt = 0; mt < 2; ++mt)
#pragma unroll
            for (int nt = 0; nt < 4; ++nt)
#pragma unroll
                for (int k = 0; k < 4; ++k) acc[mt][nt][k] = 0.f;

        const int kq0 = wK * 256;

        CP_WAIT1();
        asm volatile("bar.sync %0, 128;" :: "r"(barid) : "memory");
#pragma unroll
        for (int kk = 0; kk < 8; ++kk) {
            const int k0 = kq0 + kk * 16;
            uint32_t a[2][4];
#pragma unroll
            for (int mt = 0; mt < 2; ++mt) {
                const __half* ap = sHh + (wM * 32 + mt * 16 + gid) * RHPH + k0 + 2 * tq;
                a[mt][0] = ldu32(ap);
                a[mt][1] = ldu32(ap + 8 * RHPH);
                a[mt][2] = ldu32(ap + 8);
                a[mt][3] = ldu32(ap + 8 * RHPH + 8);
            }
#pragma unroll
            for (int nt = 0; nt < 4; ++nt) {
                const __half* bp = sWh + (wN * 32 + nt * 8 + gid) * RWPH + k0 + 2 * tq;
                uint32_t bfr[2];
                bfr[0] = ldu32(bp);
                bfr[1] = ldu32(bp + 8);
#pragma unroll
                for (int mt = 0; mt < 2; ++mt)
                    mma_f16(acc[mt][nt], a[mt], bfr);
            }
        }
        CP_WAIT0();
        asm volatile("bar.sync %0, 128;" :: "r"(barid) : "memory");
#pragma unroll
        for (int kk = 8; kk < 16; ++kk) {
            const int k0 = kq0 + kk * 16;
            uint32_t a[2][4];
#pragma unroll
            for (int mt = 0; mt < 2; ++mt) {
                const __half* ap = sHh + (wM * 32 + mt * 16 + gid) * RHPH + k0 + 2 * tq;
                a[mt][0] = ldu32(ap);
                a[mt][1] = ldu32(ap + 8 * RHPH);
                a[mt][2] = ldu32(ap + 8);
                a[mt][3] = ldu32(ap + 8 * RHPH + 8);
            }
#pragma unroll
            for (int nt = 0; nt < 4; ++nt) {
                const __half* bp = sWh + (wN * 32 + nt * 8 + gid) * RWPH + k0 + 2 * tq;
                uint32_t bfr[2];
                bfr[0] = ldu32(bp);
                bfr[1] = ldu32(bp + 8);
#pragma unroll
                for (int mt = 0; mt < 2; ++mt)
                    mma_f16(acc[mt][nt], a[mt], bfr);
            }
        }

        // ---- symmetric K-split exchange: write NON-owned mt to sRed ----
        {
            int mtx = wK ^ 1;
#pragma unroll
            for (int nt = 0; nt < 4; ++nt) {
                float4 v;
                v.x = acc[mtx][nt][0]; v.y = acc[mtx][nt][1];
                v.z = acc[mtx][nt][2]; v.w = acc[mtx][nt][3];
                *reinterpret_cast<float4*>(
                    &sRed[((wK * 4 + pair) * 4 + nt) * 128 + lane * 4]) = v;
            }
        }
        __syncthreads();                   // (2)

        // ---- finalize owned mt: add peer partials, activations, write tile
        {
            int mto = wK;
            int src = wK ^ 1;
            int rl = wM * 32 + mto * 16 + gid + p * 8;
#pragma unroll
            for (int nt = 0; nt < 4; ++nt) {
                float4 v = *reinterpret_cast<const float4*>(
                    &sRed[((src * 4 + pair) * 4 + nt) * 128 + lane * 4]);
                float q0 = acc[mto][nt][0] + v.x;
                float q1 = acc[mto][nt][1] + v.y;
                float q2 = acc[mto][nt][2] + v.z;
                float q3 = acc[mto][nt][3] + v.w;
                float s0 = p ? q0 : q2;
                float s1 = p ? q1 : q3;
                float r0 = __shfl_xor_sync(0xffffffffu, s0, 1);
                float r1 = __shfl_xor_sync(0xffffffffu, s1, 1);
                float gi = p ? r0 : q0;
                float gf = p ? r1 : q1;
                float gg = p ? q2 : r0;
                float go = p ? q3 : r1;
                int cl = wN * 8 + nt * 2 + (tq >> 1);
                const __half* xp = &sXG[rl * XGPH + cl];
                float iv = sigmoid_ap(gi + __half2float(xp[0]));
                float fv = sigmoid_ap(gf + __half2float(xp[16]));
                float gv = tanh_ap(gg + __half2float(xp[32]));
                float ov = sigmoid_ap(go + __half2float(xp[48]));
                cst[nt] = fv * cst[nt] + iv * gv;
                float hv = ov * tanh_ap(cst[nt]);
                sTrH[rl * 16 + cl] = __float2half_rn(hv);
            }
        }
        __syncthreads();                   // (2b) sTrH complete; sXG consumed

        // ---- coalesced hout write (each warp its own 8 rows) ----
        {
            int row = tid >> 2, part = tid & 3;
            uint2 v = *reinterpret_cast<const uint2*>(&sTrH[row * 16 + part * 4]);
            *reinterpret_cast<uint2*>(&hout[(size_t)(m0 + row) * Hh + hc0 + part * 4]) = v;
        }

        // ---- warp-granular arrive (release covers this warp's hout) ----
        phase += GRP_ARR;
        __syncwarp();
        if (lane == 0) {
            asm volatile("red.release.gpu.add.u32 [%0], %1;"
                         :: "l"(&g_bar[ctaM]), "r"(1u) : "memory");
        }

        // ---- non-critical work in barrier shadow: hseq + xg(t+1) ----
        if (hseq) {
            int row = tid >> 2, part = tid & 3;
            uint2 v = *reinterpret_cast<const uint2*>(&sTrH[row * 16 + part * 4]);
            *reinterpret_cast<uint2*>(
                &hseq[((size_t)(m0 + row) * Tt + t) * Hh + hc0 + part * 4]) = v;
        }
        if (t + 1 < Tt) {
#pragma unroll
            for (int it = 0; it < 2; ++it) {
                int seg = tid + it * 256;
                int row = seg >> 3, c8 = seg & 7;
                int gate = c8 >> 1, colpart = (c8 & 1) * 8;
                cpa16(sXG_u + (row * XGPH + c8 * 8) * 2,
                      &xgh[((size_t)(m0 + row) * Tt + (t + 1)) * Gg
                           + (size_t)gate * Hh + hc0 + colpart]);
            }
            CP_COMMIT();
        }

        // ---- per-warp acquire-poll ----
        if (lane == 0) {
            unsigned v;
            do {
                asm volatile("ld.acquire.gpu.u32 %0, [%1];"
                             : "=r"(v) : "l"(&g_bar[ctaM]) : "memory");
            } while (v < phase);
        }
        __syncwarp();
    }
}

// ---------------- final FC (h is fp16) --------------------------------------
__global__ void fc_kernel(const __half* __restrict__ h, const float* __restrict__ Wfc,
                          const float* __restrict__ bfc, float* __restrict__ out)
{
    int b = blockIdx.x;
    int tid = threadIdx.x;
    float s = 0.f;
    for (int k = tid; k < Hh; k += 128)
        s += __half2float(h[(size_t)b * Hh + k]) * Wfc[k];
#pragma unroll
    for (int o = 16; o > 0; o >>= 1) s += __shfl_xor_sync(0xffffffffu, s, o);
    __shared__ float ws[4];
    if ((tid & 31) == 0) ws[tid >> 5] = s;
    __syncthreads();
    if (tid == 0) out[b] = ws[0] + ws[1] + ws[2] + ws[3] + bfc[0];
}

// ---------------- launch ----------------------------------------------------
extern "C" void kernel_launch(void* const* d_in, const int* in_sizes, int n_in,
                              void* d_out, int out_size)
{
    (void)in_sizes; (void)n_in; (void)out_size;
    const float* x     = (const float*)d_in[0];
    const float* W_ih0 = (const float*)d_in[1];
    const float* W_hh0 = (const float*)d_in[2];
    const float* b_ih0 = (const float*)d_in[3];
    const float* b_hh0 = (const float*)d_in[4];
    const float* W_ih1 = (const float*)d_in[5];
    const float* W_hh1 = (const float*)d_in[6];
    const float* b_ih1 = (const float*)d_in[7];
    const float* b_hh1 = (const float*)d_in[8];
    const float* W_fc  = (const float*)d_in[9];
    const float* b_fc  = (const float*)d_in[10];
    float* out = (float*)d_out;

    void *p_xg = nullptr, *p_hseq = nullptr, *p_hbuf = nullptr;
    cudaGetSymbolAddress(&p_xg, g_xg);
    cudaGetSymbolAddress(&p_hseq, g_hseq);
    cudaGetSymbolAddress(&p_hbuf, g_hbuf);

    cudaFuncSetAttribute(mma_gemm, cudaFuncAttributeMaxDynamicSharedMemorySize,
                         GEMM_SMEM_BYTES);
    cudaFuncSetAttribute(mma_gemm_h, cudaFuncAttributeMaxDynamicSharedMemorySize,
                         GEMM_SMEM_BYTES);
    cudaFuncSetAttribute(lstm_rec, cudaFuncAttributeMaxDynamicSharedMemorySize,
                         REC_SMEM_BYTES);

    dim3 ggrid(Gg / 128, (Bb * Tt) / 128);   // (16, 1024)

    // Layer 0
    mma_gemm<<<ggrid, 256, GEMM_SMEM_BYTES>>>(x, W_ih0, b_ih0, b_hh0,
                                              (__half*)p_xg, Ii);
    init_kernel<<<1024, 256>>>();
    lstm_rec<<<NCTA_R, 256, REC_SMEM_BYTES>>>(W_hh0, (const __half*)p_xg,
                                              (__half*)p_hseq);

    // Layer 1 (A = fp16 hseq)
    mma_gemm_h<<<ggrid, 256, GEMM_SMEM_BYTES>>>((const __half*)p_hseq, W_ih1,
                                                b_ih1, b_hh1, (__half*)p_xg, Hh);
    init_kernel<<<1024, 256>>>();
    lstm_rec<<<NCTA_R, 256, REC_SMEM_BYTES>>>(W_hh1, (const __half*)p_xg, nullptr);

    // Final FC (h_last ends in buffer 0 since T=512 is even; fp16 layout)
    fc_kernel<<<Bb, 128>>>((const __half*)p_hbuf, W_fc, b_fc, out);
}